// round 3
// baseline (speedup 1.0000x reference)
#include <cuda_runtime.h>
#include <math.h>

// Problem dims
#define Tt   128
#define Bb   64
#define Ff   512
#define Hh   1024
#define NG   4096     // 4*H (gate-interleaved columns: col = 4h+g)
#define TBm  8192     // T*B
#define OUTF 513      // F+1
#define HB   (Hh*Bb)  // 65536
#define NBLK 128      // persistent grid: one block per SM, single wave
#define CK   128      // K-chunk rows for h streaming

// ---------------- scratch (device globals; no allocations allowed) ----------
static __device__ float d_Wcat[(size_t)Ff * NG];            // 8 MB   [k][4h+g]
static __device__ float d_Ucat[(size_t)Hh * NG];            // 16 MB  [k][4h+g]
static __device__ float d_Bcat[NG];
static __device__ float d_G[(size_t)TBm * NG];              // 128 MB gate pre-activations
static __device__ float d_Hbuf[(size_t)TBm * Hh];           // 32 MB  h_t, [t*B+b][h] (for out GEMM)
static __device__ float d_hT[(size_t)Tt * HB];              // 32 MB  h_t transposed [t][h][b]
static __device__ unsigned g_bar;                           // grid barrier counter

// Hamilton block tables
__constant__ int   c_CM[16] = {0,1,2,3,  1,0,3,2,  2,3,0,1,  3,2,1,0};
__constant__ float c_SG[16] = {1.f,1.f,1.f,1.f,  -1.f,1.f,1.f,-1.f,
                               -1.f,-1.f,1.f,1.f,  -1.f,1.f,-1.f,1.f};

// ---------------- build dense Hamilton matrices -----------------------------
__global__ void k_build_w(const float* __restrict__ wf, const float* __restrict__ wi,
                          const float* __restrict__ wo, const float* __restrict__ wc) {
    int idx = blockIdx.x * blockDim.x + threadIdx.x;
    if (idx >= Ff * NG) return;
    int k = idx >> 12;
    int c = idx & (NG - 1);
    int g  = c & 3;
    int hh = c >> 2;
    int cb = hh >> 8, bb = hh & 255;
    int rb = k >> 7,  aa = k & 127;
    const float* w = (g == 0) ? wf : (g == 1) ? wi : (g == 2) ? wo : wc;
    int m = rb * 4 + cb;
    d_Wcat[idx] = c_SG[m] * w[((size_t)c_CM[m] * 128 + aa) * 256 + bb];
}

__global__ void k_build_u(const float* __restrict__ uf, const float* __restrict__ ui,
                          const float* __restrict__ uo, const float* __restrict__ uc) {
    int idx = blockIdx.x * blockDim.x + threadIdx.x;
    if (idx >= Hh * NG) return;
    int k = idx >> 12;
    int c = idx & (NG - 1);
    int g  = c & 3;
    int hh = c >> 2;
    int cb = hh >> 8, bb = hh & 255;
    int rb = k >> 8,  aa = k & 255;
    const float* w = (g == 0) ? uf : (g == 1) ? ui : (g == 2) ? uo : uc;
    int m = rb * 4 + cb;
    d_Ucat[idx] = c_SG[m] * w[((size_t)c_CM[m] * 256 + aa) * 256 + bb];
}

__global__ void k_build_misc(const float* __restrict__ bf, const float* __restrict__ bi,
                             const float* __restrict__ bo, const float* __restrict__ bc) {
    int idx = blockIdx.x * blockDim.x + threadIdx.x;
    if (idx == 0) g_bar = 0u;
    if (idx < NG) {
        int g = idx & 3, hh = idx >> 2;
        const float* b = (g == 0) ? bf : (g == 1) ? bi : (g == 2) ? bo : bc;
        d_Bcat[idx] = b[hh];
    }
}

// ---------------- input GEMM: G = x @ Wcat + Bcat ---------------------------
__global__ __launch_bounds__(256) void k_gemm_in(const float* __restrict__ X) {
    __shared__ __align__(16) float As[8][128];
    __shared__ __align__(16) float Bs[8][128];
    const int bn = blockIdx.x, bm = blockIdx.y;
    const int tid = threadIdx.x;
    const int tx = tid & 15, ty = tid >> 4;
    const int row0 = bm * 128, col0 = bn * 128;
    float acc[8][8];
#pragma unroll
    for (int i = 0; i < 8; i++)
#pragma unroll
        for (int j = 0; j < 8; j++) acc[i][j] = 0.f;

    const int am = tid >> 1, ak = (tid & 1) * 4;
    const int bk = tid >> 5, bn4 = (tid & 31) * 4;

    for (int k0 = 0; k0 < Ff; k0 += 8) {
        float4 av = *(const float4*)&X[(size_t)(row0 + am) * Ff + k0 + ak];
        float4 bv = *(const float4*)&d_Wcat[(size_t)(k0 + bk) * NG + col0 + bn4];
        As[ak + 0][am] = av.x; As[ak + 1][am] = av.y;
        As[ak + 2][am] = av.z; As[ak + 3][am] = av.w;
        *(float4*)&Bs[bk][bn4] = bv;
        __syncthreads();
#pragma unroll
        for (int kk = 0; kk < 8; kk++) {
            float a[8], b[8];
            *(float4*)(a)     = *(float4*)&As[kk][ty * 8];
            *(float4*)(a + 4) = *(float4*)&As[kk][ty * 8 + 4];
            *(float4*)(b)     = *(float4*)&Bs[kk][tx * 8];
            *(float4*)(b + 4) = *(float4*)&Bs[kk][tx * 8 + 4];
#pragma unroll
            for (int i = 0; i < 8; i++)
#pragma unroll
                for (int j = 0; j < 8; j++)
                    acc[i][j] = fmaf(a[i], b[j], acc[i][j]);
        }
        __syncthreads();
    }
#pragma unroll
    for (int i = 0; i < 8; i++) {
        size_t row = (size_t)(row0 + ty * 8 + i);
#pragma unroll
        for (int j = 0; j < 8; j += 4) {
            int col = col0 + tx * 8 + j;
            float4 o;
            o.x = acc[i][j]     + d_Bcat[col];
            o.y = acc[i][j + 1] + d_Bcat[col + 1];
            o.z = acc[i][j + 2] + d_Bcat[col + 2];
            o.w = acc[i][j + 3] + d_Bcat[col + 3];
            *(float4*)&d_G[row * NG + col] = o;
        }
    }
}

// ---------------- persistent fused recurrence -------------------------------
// 128 blocks x 256 threads. Block owns 32 gate-interleaved columns (8 h units).
// Full K=1024 U-slice resident in smem; h streamed; cell state in registers.
__device__ __forceinline__ void grid_bar(unsigned target) {
    __syncthreads();
    if (threadIdx.x == 0) {
        __threadfence();
        atomicAdd(&g_bar, 1u);
        while (*(volatile unsigned*)&g_bar < target) { }
        __threadfence();
    }
    __syncthreads();
}

__global__ __launch_bounds__(256, 1) void k_recur() {
    extern __shared__ float sm[];
    float* Us = sm;                      // [1024][32]  U slice (128 KB), resident
    float* Hs = sm + 1024 * 32;          // [2][CK][64] h chunk double buffer (64 KB)
    const int tid = threadIdx.x;
    const int blk = blockIdx.x;
    const int tx  = tid & 7;             // col quad 0..7
    const int ty  = tid >> 3;            // row pair 0..31
    const int c0  = blk * 32;            // first gate-interleaved column
    const int hidx = blk * 8 + tx;       // hidden unit this thread's 4 cols belong to
    const int b0 = ty * 2, b1 = ty * 2 + 1;

    // Load U slice once (reused for all 127 steps)
#pragma unroll
    for (int w = 0; w < 32; w++) {
        int idx = tid + w * 256;
        int row = idx >> 3, lc = (idx & 7) * 4;
        *(float4*)&Us[row * 32 + lc] = *(const float4*)&d_Ucat[(size_t)row * NG + c0 + lc];
    }

    float creg[2] = {0.f, 0.f};

    // ---- t = 0: h_{-1} = 0 -> Z = G only ----
    {
        float4 g0 = *(const float4*)&d_G[(size_t)b0 * NG + c0 + tx * 4];
        float4 g1 = *(const float4*)&d_G[(size_t)b1 * NG + c0 + tx * 4];
        float zf, zi, zo, za, f, ii, o, cc, hn;
        // row 0
        zf = g0.x; zi = g0.y; zo = g0.z; za = g0.w;
        f = 1.f/(1.f+expf(-zf)); ii = 1.f/(1.f+expf(-zi)); o = 1.f/(1.f+expf(-zo));
        cc = ii * tanhf(za) + f * creg[0]; creg[0] = cc; hn = o * tanhf(cc);
        d_hT[(size_t)hidx * 64 + b0] = hn;
        d_Hbuf[(size_t)b0 * Hh + hidx] = hn;
        // row 1
        zf = g1.x; zi = g1.y; zo = g1.z; za = g1.w;
        f = 1.f/(1.f+expf(-zf)); ii = 1.f/(1.f+expf(-zi)); o = 1.f/(1.f+expf(-zo));
        cc = ii * tanhf(za) + f * creg[1]; creg[1] = cc; hn = o * tanhf(cc);
        d_hT[(size_t)hidx * 64 + b1] = hn;
        d_Hbuf[(size_t)b1 * Hh + hidx] = hn;
    }

    for (int t = 1; t < Tt; t++) {
        grid_bar((unsigned)t * NBLK);    // h_{t-1} fully written & visible

        const float* hp = &d_hT[(size_t)(t - 1) * HB];

        // prefetch G for this thread's elements (overlaps with GEMM)
        float4 g0 = *(const float4*)&d_G[((size_t)t * Bb + b0) * NG + c0 + tx * 4];
        float4 g1 = *(const float4*)&d_G[((size_t)t * Bb + b1) * NG + c0 + tx * 4];

        // preload chunk 0
#pragma unroll
        for (int j = 0; j < 8; j++) {
            int f4 = tid + j * 256;
            *(float4*)&Hs[f4 * 4] = *(const float4*)&hp[f4 * 4];
        }
        __syncthreads();

        float acc0[4] = {0.f, 0.f, 0.f, 0.f};
        float acc1[4] = {0.f, 0.f, 0.f, 0.f};

        for (int c = 0; c < Hh / CK; c++) {
            float4 r[8];
            if (c < Hh / CK - 1) {
                const float* np = hp + (size_t)(c + 1) * CK * 64;
#pragma unroll
                for (int j = 0; j < 8; j++) r[j] = *(const float4*)&np[(tid + j * 256) * 4];
            }
            const float* hb = &Hs[(c & 1) * CK * 64];
            const float* ub = &Us[c * CK * 32];
#pragma unroll 8
            for (int kk = 0; kk < CK; kk++) {
                float2 a = *(const float2*)&hb[kk * 64 + ty * 2];
                float4 b = *(const float4*)&ub[kk * 32 + tx * 4];
                acc0[0] = fmaf(a.x, b.x, acc0[0]);
                acc0[1] = fmaf(a.x, b.y, acc0[1]);
                acc0[2] = fmaf(a.x, b.z, acc0[2]);
                acc0[3] = fmaf(a.x, b.w, acc0[3]);
                acc1[0] = fmaf(a.y, b.x, acc1[0]);
                acc1[1] = fmaf(a.y, b.y, acc1[1]);
                acc1[2] = fmaf(a.y, b.z, acc1[2]);
                acc1[3] = fmaf(a.y, b.w, acc1[3]);
            }
            if (c < Hh / CK - 1) {
                float* nb = &Hs[((c + 1) & 1) * CK * 64];
#pragma unroll
                for (int j = 0; j < 8; j++) *(float4*)&nb[(tid + j * 256) * 4] = r[j];
                __syncthreads();
            }
        }

        // fused pointwise: gates + cell update + h writes (state in registers)
        {
            float zf, zi, zo, za, f, ii, o, cc, hn;
            zf = g0.x + acc0[0]; zi = g0.y + acc0[1];
            zo = g0.z + acc0[2]; za = g0.w + acc0[3];
            f = 1.f/(1.f+expf(-zf)); ii = 1.f/(1.f+expf(-zi)); o = 1.f/(1.f+expf(-zo));
            cc = ii * tanhf(za) + f * creg[0]; creg[0] = cc; hn = o * tanhf(cc);
            d_hT[(size_t)t * HB + (size_t)hidx * 64 + b0] = hn;
            d_Hbuf[((size_t)t * Bb + b0) * Hh + hidx] = hn;

            zf = g1.x + acc1[0]; zi = g1.y + acc1[1];
            zo = g1.z + acc1[2]; za = g1.w + acc1[3];
            f = 1.f/(1.f+expf(-zf)); ii = 1.f/(1.f+expf(-zi)); o = 1.f/(1.f+expf(-zo));
            cc = ii * tanhf(za) + f * creg[1]; creg[1] = cc; hn = o * tanhf(cc);
            d_hT[(size_t)t * HB + (size_t)hidx * 64 + b1] = hn;
            d_Hbuf[((size_t)t * Bb + b1) * Hh + hidx] = hn;
        }
    }
}

// ---------------- output GEMM: Out = Hbuf @ fco_w + fco_b -------------------
__global__ __launch_bounds__(256) void k_gemm_out(const float* __restrict__ Wout,
                                                  const float* __restrict__ bout,
                                                  float* __restrict__ Out) {
    __shared__ __align__(16) float As[8][128];
    __shared__ __align__(16) float Bs[8][128];
    const int bn = blockIdx.x, bm = blockIdx.y;
    const int tid = threadIdx.x;
    const int tx = tid & 15, ty = tid >> 4;
    const int row0 = bm * 128, col0 = bn * 128;
    float acc[8][8];
#pragma unroll
    for (int i = 0; i < 8; i++)
#pragma unroll
        for (int j = 0; j < 8; j++) acc[i][j] = 0.f;

    const int am = tid >> 1, ak = (tid & 1) * 4;
    const int bk = tid >> 5, bn4 = (tid & 31) * 4;

    for (int k0 = 0; k0 < Hh; k0 += 8) {
        float4 av = *(const float4*)&d_Hbuf[(size_t)(row0 + am) * Hh + k0 + ak];
        As[ak + 0][am] = av.x; As[ak + 1][am] = av.y;
        As[ak + 2][am] = av.z; As[ak + 3][am] = av.w;
#pragma unroll
        for (int e = 0; e < 4; e++) {
            int n = col0 + bn4 + e;
            Bs[bk][bn4 + e] = (n < OUTF) ? Wout[(size_t)(k0 + bk) * OUTF + n] : 0.f;
        }
        __syncthreads();
#pragma unroll
        for (int kk = 0; kk < 8; kk++) {
            float a[8], b[8];
            *(float4*)(a)     = *(float4*)&As[kk][ty * 8];
            *(float4*)(a + 4) = *(float4*)&As[kk][ty * 8 + 4];
            *(float4*)(b)     = *(float4*)&Bs[kk][tx * 8];
            *(float4*)(b + 4) = *(float4*)&Bs[kk][tx * 8 + 4];
#pragma unroll
            for (int i = 0; i < 8; i++)
#pragma unroll
                for (int j = 0; j < 8; j++)
                    acc[i][j] = fmaf(a[i], b[j], acc[i][j]);
        }
        __syncthreads();
    }
#pragma unroll
    for (int i = 0; i < 8; i++) {
        size_t row = (size_t)(row0 + ty * 8 + i);
#pragma unroll
        for (int j = 0; j < 8; j++) {
            int col = col0 + tx * 8 + j;
            if (col < OUTF)
                Out[row * OUTF + col] = acc[i][j] + bout[col];
        }
    }
}

// ---------------- launch --------------------------------------------------
extern "C" void kernel_launch(void* const* d_in, const int* in_sizes, int n_in,
                              void* d_out, int out_size) {
    (void)in_sizes; (void)n_in; (void)out_size;
    const float* x     = (const float*)d_in[0];
    const float* wfx_w = (const float*)d_in[1];
    const float* wfx_b = (const float*)d_in[2];
    const float* wix_w = (const float*)d_in[3];
    const float* wix_b = (const float*)d_in[4];
    const float* wox_w = (const float*)d_in[5];
    const float* wox_b = (const float*)d_in[6];
    const float* wcx_w = (const float*)d_in[7];
    const float* wcx_b = (const float*)d_in[8];
    const float* ufh_w = (const float*)d_in[9];
    const float* uih_w = (const float*)d_in[10];
    const float* uoh_w = (const float*)d_in[11];
    const float* uch_w = (const float*)d_in[12];
    const float* fco_w = (const float*)d_in[13];
    const float* fco_b = (const float*)d_in[14];
    float* out = (float*)d_out;

    const int recurSmem = (1024 * 32 + 2 * CK * 64) * (int)sizeof(float);  // 192 KB
    cudaFuncSetAttribute(k_recur, cudaFuncAttributeMaxDynamicSharedMemorySize, recurSmem);

    k_build_w<<<(Ff * NG + 255) / 256, 256>>>(wfx_w, wix_w, wox_w, wcx_w);
    k_build_u<<<(Hh * NG + 255) / 256, 256>>>(ufh_w, uih_w, uoh_w, uch_w);
    k_build_misc<<<(NG + 255) / 256, 256>>>(wfx_b, wix_b, wox_b, wcx_b);

    k_gemm_in<<<dim3(NG / 128, TBm / 128), 256>>>(x);

    k_recur<<<NBLK, 256, recurSmem>>>();

    k_gemm_out<<<dim3((OUTF + 127) / 128, TBm / 128), 256>>>(fco_w, fco_b, out);
}

// round 4
// speedup vs baseline: 1.0005x; 1.0005x over previous
#include <cuda_runtime.h>
#include <math.h>

// Problem dims
#define Tt   128
#define Bb   64
#define Ff   512
#define Hh   1024
#define NG   4096     // 4*H (gate-interleaved columns: col = 4h+g)
#define TBm  8192     // T*B
#define OUTF 513      // F+1
#define HB   (Hh*Bb)  // 65536
#define NBLK 128      // persistent grid: one block per SM, single wave
#define CK   128      // K-chunk rows for h streaming

// ---------------- scratch (device globals; no allocations allowed) ----------
static __device__ float d_Wcat[(size_t)Ff * NG];            // 8 MB   [k][4h+g]
static __device__ float d_Ucat[(size_t)Hh * NG];            // 16 MB  [k][4h+g]
static __device__ float d_Bcat[NG];
static __device__ float d_G[(size_t)TBm * NG];              // 128 MB gate pre-activations
static __device__ float d_Hbuf[(size_t)TBm * Hh];           // 32 MB  h_t, [t*B+b][h] (for out GEMM)
static __device__ float d_hT[(size_t)Tt * HB];              // 32 MB  h_t transposed [t][h][b]
static __device__ unsigned g_bar;                           // grid barrier counter

// Hamilton block tables
__constant__ int   c_CM[16] = {0,1,2,3,  1,0,3,2,  2,3,0,1,  3,2,1,0};
__constant__ float c_SG[16] = {1.f,1.f,1.f,1.f,  -1.f,1.f,1.f,-1.f,
                               -1.f,-1.f,1.f,1.f,  -1.f,1.f,-1.f,1.f};

// ---------------- build dense Hamilton matrices -----------------------------
__global__ void k_build_w(const float* __restrict__ wf, const float* __restrict__ wi,
                          const float* __restrict__ wo, const float* __restrict__ wc) {
    int idx = blockIdx.x * blockDim.x + threadIdx.x;
    if (idx >= Ff * NG) return;
    int k = idx >> 12;
    int c = idx & (NG - 1);
    int g  = c & 3;
    int hh = c >> 2;
    int cb = hh >> 8, bb = hh & 255;
    int rb = k >> 7,  aa = k & 127;
    const float* w = (g == 0) ? wf : (g == 1) ? wi : (g == 2) ? wo : wc;
    int m = rb * 4 + cb;
    d_Wcat[idx] = c_SG[m] * w[((size_t)c_CM[m] * 128 + aa) * 256 + bb];
}

__global__ void k_build_u(const float* __restrict__ uf, const float* __restrict__ ui,
                          const float* __restrict__ uo, const float* __restrict__ uc) {
    int idx = blockIdx.x * blockDim.x + threadIdx.x;
    if (idx >= Hh * NG) return;
    int k = idx >> 12;
    int c = idx & (NG - 1);
    int g  = c & 3;
    int hh = c >> 2;
    int cb = hh >> 8, bb = hh & 255;
    int rb = k >> 8,  aa = k & 255;
    const float* w = (g == 0) ? uf : (g == 1) ? ui : (g == 2) ? uo : uc;
    int m = rb * 4 + cb;
    d_Ucat[idx] = c_SG[m] * w[((size_t)c_CM[m] * 256 + aa) * 256 + bb];
}

__global__ void k_build_misc(const float* __restrict__ bf, const float* __restrict__ bi,
                             const float* __restrict__ bo, const float* __restrict__ bc) {
    int idx = blockIdx.x * blockDim.x + threadIdx.x;
    if (idx == 0) g_bar = 0u;
    if (idx < NG) {
        int g = idx & 3, hh = idx >> 2;
        const float* b = (g == 0) ? bf : (g == 1) ? bi : (g == 2) ? bo : bc;
        d_Bcat[idx] = b[hh];
    }
}

// ---------------- input GEMM: G = x @ Wcat + Bcat ---------------------------
__global__ __launch_bounds__(256) void k_gemm_in(const float* __restrict__ X) {
    __shared__ __align__(16) float As[8][128];
    __shared__ __align__(16) float Bs[8][128];
    const int bn = blockIdx.x, bm = blockIdx.y;
    const int tid = threadIdx.x;
    const int tx = tid & 15, ty = tid >> 4;
    const int row0 = bm * 128, col0 = bn * 128;
    float acc[8][8];
#pragma unroll
    for (int i = 0; i < 8; i++)
#pragma unroll
        for (int j = 0; j < 8; j++) acc[i][j] = 0.f;

    const int am = tid >> 1, ak = (tid & 1) * 4;
    const int bk = tid >> 5, bn4 = (tid & 31) * 4;

    for (int k0 = 0; k0 < Ff; k0 += 8) {
        float4 av = *(const float4*)&X[(size_t)(row0 + am) * Ff + k0 + ak];
        float4 bv = *(const float4*)&d_Wcat[(size_t)(k0 + bk) * NG + col0 + bn4];
        As[ak + 0][am] = av.x; As[ak + 1][am] = av.y;
        As[ak + 2][am] = av.z; As[ak + 3][am] = av.w;
        *(float4*)&Bs[bk][bn4] = bv;
        __syncthreads();
#pragma unroll
        for (int kk = 0; kk < 8; kk++) {
            float a[8], b[8];
            *(float4*)(a)     = *(float4*)&As[kk][ty * 8];
            *(float4*)(a + 4) = *(float4*)&As[kk][ty * 8 + 4];
            *(float4*)(b)     = *(float4*)&Bs[kk][tx * 8];
            *(float4*)(b + 4) = *(float4*)&Bs[kk][tx * 8 + 4];
#pragma unroll
            for (int i = 0; i < 8; i++)
#pragma unroll
                for (int j = 0; j < 8; j++)
                    acc[i][j] = fmaf(a[i], b[j], acc[i][j]);
        }
        __syncthreads();
    }
#pragma unroll
    for (int i = 0; i < 8; i++) {
        size_t row = (size_t)(row0 + ty * 8 + i);
#pragma unroll
        for (int j = 0; j < 8; j += 4) {
            int col = col0 + tx * 8 + j;
            float4 o;
            o.x = acc[i][j]     + d_Bcat[col];
            o.y = acc[i][j + 1] + d_Bcat[col + 1];
            o.z = acc[i][j + 2] + d_Bcat[col + 2];
            o.w = acc[i][j + 3] + d_Bcat[col + 3];
            *(float4*)&d_G[row * NG + col] = o;
        }
    }
}

// ---------------- persistent fused recurrence -------------------------------
// 128 blocks x 256 threads. Block owns 32 gate-interleaved columns (8 h units).
// Full K=1024 U-slice resident in smem; h streamed; cell state in registers.
__device__ __forceinline__ void grid_bar(unsigned target) {
    __syncthreads();
    if (threadIdx.x == 0) {
        __threadfence();
        atomicAdd(&g_bar, 1u);
        while (*(volatile unsigned*)&g_bar < target) { }
        __threadfence();
    }
    __syncthreads();
}

__global__ __launch_bounds__(256, 1) void k_recur() {
    extern __shared__ float sm[];
    float* Us = sm;                      // [1024][32]  U slice (128 KB), resident
    float* Hs = sm + 1024 * 32;          // [2][CK][64] h chunk double buffer (64 KB)
    const int tid = threadIdx.x;
    const int blk = blockIdx.x;
    const int tx  = tid & 7;             // col quad 0..7
    const int ty  = tid >> 3;            // row pair 0..31
    const int c0  = blk * 32;            // first gate-interleaved column
    const int hidx = blk * 8 + tx;       // hidden unit this thread's 4 cols belong to
    const int b0 = ty * 2, b1 = ty * 2 + 1;

    // Load U slice once (reused for all 127 steps)
#pragma unroll
    for (int w = 0; w < 32; w++) {
        int idx = tid + w * 256;
        int row = idx >> 3, lc = (idx & 7) * 4;
        *(float4*)&Us[row * 32 + lc] = *(const float4*)&d_Ucat[(size_t)row * NG + c0 + lc];
    }

    float creg[2] = {0.f, 0.f};

    // ---- t = 0: h_{-1} = 0 -> Z = G only ----
    {
        float4 g0 = *(const float4*)&d_G[(size_t)b0 * NG + c0 + tx * 4];
        float4 g1 = *(const float4*)&d_G[(size_t)b1 * NG + c0 + tx * 4];
        float zf, zi, zo, za, f, ii, o, cc, hn;
        // row 0
        zf = g0.x; zi = g0.y; zo = g0.z; za = g0.w;
        f = 1.f/(1.f+expf(-zf)); ii = 1.f/(1.f+expf(-zi)); o = 1.f/(1.f+expf(-zo));
        cc = ii * tanhf(za) + f * creg[0]; creg[0] = cc; hn = o * tanhf(cc);
        d_hT[(size_t)hidx * 64 + b0] = hn;
        d_Hbuf[(size_t)b0 * Hh + hidx] = hn;
        // row 1
        zf = g1.x; zi = g1.y; zo = g1.z; za = g1.w;
        f = 1.f/(1.f+expf(-zf)); ii = 1.f/(1.f+expf(-zi)); o = 1.f/(1.f+expf(-zo));
        cc = ii * tanhf(za) + f * creg[1]; creg[1] = cc; hn = o * tanhf(cc);
        d_hT[(size_t)hidx * 64 + b1] = hn;
        d_Hbuf[(size_t)b1 * Hh + hidx] = hn;
    }

    for (int t = 1; t < Tt; t++) {
        grid_bar((unsigned)t * NBLK);    // h_{t-1} fully written & visible

        const float* hp = &d_hT[(size_t)(t - 1) * HB];

        // prefetch G for this thread's elements (overlaps with GEMM)
        float4 g0 = *(const float4*)&d_G[((size_t)t * Bb + b0) * NG + c0 + tx * 4];
        float4 g1 = *(const float4*)&d_G[((size_t)t * Bb + b1) * NG + c0 + tx * 4];

        // preload chunk 0
#pragma unroll
        for (int j = 0; j < 8; j++) {
            int f4 = tid + j * 256;
            *(float4*)&Hs[f4 * 4] = *(const float4*)&hp[f4 * 4];
        }
        __syncthreads();

        float acc0[4] = {0.f, 0.f, 0.f, 0.f};
        float acc1[4] = {0.f, 0.f, 0.f, 0.f};

        for (int c = 0; c < Hh / CK; c++) {
            float4 r[8];
            if (c < Hh / CK - 1) {
                const float* np = hp + (size_t)(c + 1) * CK * 64;
#pragma unroll
                for (int j = 0; j < 8; j++) r[j] = *(const float4*)&np[(tid + j * 256) * 4];
            }
            const float* hb = &Hs[(c & 1) * CK * 64];
            const float* ub = &Us[c * CK * 32];
#pragma unroll 8
            for (int kk = 0; kk < CK; kk++) {
                float2 a = *(const float2*)&hb[kk * 64 + ty * 2];
                float4 b = *(const float4*)&ub[kk * 32 + tx * 4];
                acc0[0] = fmaf(a.x, b.x, acc0[0]);
                acc0[1] = fmaf(a.x, b.y, acc0[1]);
                acc0[2] = fmaf(a.x, b.z, acc0[2]);
                acc0[3] = fmaf(a.x, b.w, acc0[3]);
                acc1[0] = fmaf(a.y, b.x, acc1[0]);
                acc1[1] = fmaf(a.y, b.y, acc1[1]);
                acc1[2] = fmaf(a.y, b.z, acc1[2]);
                acc1[3] = fmaf(a.y, b.w, acc1[3]);
            }
            if (c < Hh / CK - 1) {
                float* nb = &Hs[((c + 1) & 1) * CK * 64];
#pragma unroll
                for (int j = 0; j < 8; j++) *(float4*)&nb[(tid + j * 256) * 4] = r[j];
                __syncthreads();
            }
        }

        // fused pointwise: gates + cell update + h writes (state in registers)
        {
            float zf, zi, zo, za, f, ii, o, cc, hn;
            zf = g0.x + acc0[0]; zi = g0.y + acc0[1];
            zo = g0.z + acc0[2]; za = g0.w + acc0[3];
            f = 1.f/(1.f+expf(-zf)); ii = 1.f/(1.f+expf(-zi)); o = 1.f/(1.f+expf(-zo));
            cc = ii * tanhf(za) + f * creg[0]; creg[0] = cc; hn = o * tanhf(cc);
            d_hT[(size_t)t * HB + (size_t)hidx * 64 + b0] = hn;
            d_Hbuf[((size_t)t * Bb + b0) * Hh + hidx] = hn;

            zf = g1.x + acc1[0]; zi = g1.y + acc1[1];
            zo = g1.z + acc1[2]; za = g1.w + acc1[3];
            f = 1.f/(1.f+expf(-zf)); ii = 1.f/(1.f+expf(-zi)); o = 1.f/(1.f+expf(-zo));
            cc = ii * tanhf(za) + f * creg[1]; creg[1] = cc; hn = o * tanhf(cc);
            d_hT[(size_t)t * HB + (size_t)hidx * 64 + b1] = hn;
            d_Hbuf[((size_t)t * Bb + b1) * Hh + hidx] = hn;
        }
    }
}

// ---------------- output GEMM: Out = Hbuf @ fco_w + fco_b -------------------
__global__ __launch_bounds__(256) void k_gemm_out(const float* __restrict__ Wout,
                                                  const float* __restrict__ bout,
                                                  float* __restrict__ Out) {
    __shared__ __align__(16) float As[8][128];
    __shared__ __align__(16) float Bs[8][128];
    const int bn = blockIdx.x, bm = blockIdx.y;
    const int tid = threadIdx.x;
    const int tx = tid & 15, ty = tid >> 4;
    const int row0 = bm * 128, col0 = bn * 128;
    float acc[8][8];
#pragma unroll
    for (int i = 0; i < 8; i++)
#pragma unroll
        for (int j = 0; j < 8; j++) acc[i][j] = 0.f;

    const int am = tid >> 1, ak = (tid & 1) * 4;
    const int bk = tid >> 5, bn4 = (tid & 31) * 4;

    for (int k0 = 0; k0 < Hh; k0 += 8) {
        float4 av = *(const float4*)&d_Hbuf[(size_t)(row0 + am) * Hh + k0 + ak];
        As[ak + 0][am] = av.x; As[ak + 1][am] = av.y;
        As[ak + 2][am] = av.z; As[ak + 3][am] = av.w;
#pragma unroll
        for (int e = 0; e < 4; e++) {
            int n = col0 + bn4 + e;
            Bs[bk][bn4 + e] = (n < OUTF) ? Wout[(size_t)(k0 + bk) * OUTF + n] : 0.f;
        }
        __syncthreads();
#pragma unroll
        for (int kk = 0; kk < 8; kk++) {
            float a[8], b[8];
            *(float4*)(a)     = *(float4*)&As[kk][ty * 8];
            *(float4*)(a + 4) = *(float4*)&As[kk][ty * 8 + 4];
            *(float4*)(b)     = *(float4*)&Bs[kk][tx * 8];
            *(float4*)(b + 4) = *(float4*)&Bs[kk][tx * 8 + 4];
#pragma unroll
            for (int i = 0; i < 8; i++)
#pragma unroll
                for (int j = 0; j < 8; j++)
                    acc[i][j] = fmaf(a[i], b[j], acc[i][j]);
        }
        __syncthreads();
    }
#pragma unroll
    for (int i = 0; i < 8; i++) {
        size_t row = (size_t)(row0 + ty * 8 + i);
#pragma unroll
        for (int j = 0; j < 8; j++) {
            int col = col0 + tx * 8 + j;
            if (col < OUTF)
                Out[row * OUTF + col] = acc[i][j] + bout[col];
        }
    }
}

// ---------------- launch --------------------------------------------------
extern "C" void kernel_launch(void* const* d_in, const int* in_sizes, int n_in,
                              void* d_out, int out_size) {
    (void)in_sizes; (void)n_in; (void)out_size;
    const float* x     = (const float*)d_in[0];
    const float* wfx_w = (const float*)d_in[1];
    const float* wfx_b = (const float*)d_in[2];
    const float* wix_w = (const float*)d_in[3];
    const float* wix_b = (const float*)d_in[4];
    const float* wox_w = (const float*)d_in[5];
    const float* wox_b = (const float*)d_in[6];
    const float* wcx_w = (const float*)d_in[7];
    const float* wcx_b = (const float*)d_in[8];
    const float* ufh_w = (const float*)d_in[9];
    const float* uih_w = (const float*)d_in[10];
    const float* uoh_w = (const float*)d_in[11];
    const float* uch_w = (const float*)d_in[12];
    const float* fco_w = (const float*)d_in[13];
    const float* fco_b = (const float*)d_in[14];
    float* out = (float*)d_out;

    const int recurSmem = (1024 * 32 + 2 * CK * 64) * (int)sizeof(float);  // 192 KB
    cudaFuncSetAttribute(k_recur, cudaFuncAttributeMaxDynamicSharedMemorySize, recurSmem);

    k_build_w<<<(Ff * NG + 255) / 256, 256>>>(wfx_w, wix_w, wox_w, wcx_w);
    k_build_u<<<(Hh * NG + 255) / 256, 256>>>(ufh_w, uih_w, uoh_w, uch_w);
    k_build_misc<<<(NG + 255) / 256, 256>>>(wfx_b, wix_b, wox_b, wcx_b);

    k_gemm_in<<<dim3(NG / 128, TBm / 128), 256>>>(x);

    k_recur<<<NBLK, 256, recurSmem>>>();

    k_gemm_out<<<dim3((OUTF + 127) / 128, TBm / 128), 256>>>(fco_w, fco_b, out);
}

// round 6
// speedup vs baseline: 1.7056x; 1.7049x over previous
#include <cuda_runtime.h>
#include <cuda_bf16.h>
#include <cstdint>
#include <math.h>

#define Tt 128
#define Bb 64
#define Ff 512
#define Hh 1024
#define NG 4096
#define TBm 8192
#define OUTF 513
#define NBLK 128

static __device__ float d_Wcat[(size_t)Ff*NG];
static __device__ float d_Bcat[NG];
static __device__ float d_G[(size_t)TBm*NG];
static __device__ float d_Hbuf[(size_t)TBm*Hh];
static __device__ __nv_bfloat16 d_Ubhi[(size_t)Hh*NG];
static __device__ __nv_bfloat16 d_Ublo[(size_t)Hh*NG];
static __device__ __nv_bfloat16 d_h2hi[2][Bb*Hh];
static __device__ __nv_bfloat16 d_h2lo[2][Bb*Hh];
static __device__ unsigned g_bar;

__constant__ int   c_CM[16] = {0,1,2,3, 1,0,3,2, 2,3,0,1, 3,2,1,0};
__constant__ float c_SG[16] = {1,1,1,1, -1,1,1,-1, -1,-1,1,1, -1,1,-1,1};

// ---- warp-mma helpers (sm_80+ PTX, valid on sm_103) ----
__device__ __forceinline__ uint32_t smem_u32(const void* p){
    uint32_t a; asm("{ .reg .u64 t; cvta.to.shared.u64 t, %1; cvt.u32.u64 %0, t; }":"=r"(a):"l"(p)); return a;
}
#define LDSM4(r,a) asm volatile("ldmatrix.sync.aligned.m8n8.x4.shared.b16 {%0,%1,%2,%3}, [%4];" \
    :"=r"((r)[0]),"=r"((r)[1]),"=r"((r)[2]),"=r"((r)[3]):"r"(a))
#define LDSM4T(r,a) asm volatile("ldmatrix.sync.aligned.m8n8.x4.trans.shared.b16 {%0,%1,%2,%3}, [%4];" \
    :"=r"((r)[0]),"=r"((r)[1]),"=r"((r)[2]),"=r"((r)[3]):"r"(a))
#define MMA16816(c,a,b0,b1) asm volatile( \
    "mma.sync.aligned.m16n8k16.row.col.f32.bf16.bf16.f32 {%0,%1,%2,%3},{%4,%5,%6,%7},{%8,%9},{%0,%1,%2,%3};" \
    :"+f"((c)[0]),"+f"((c)[1]),"+f"((c)[2]),"+f"((c)[3]) \
    :"r"((a)[0]),"r"((a)[1]),"r"((a)[2]),"r"((a)[3]),"r"(b0),"r"(b1))

// ---- builds (gate-interleaved cols: col = 4h + g) ----
__global__ void k_build_w(const float* __restrict__ wf, const float* __restrict__ wi,
                          const float* __restrict__ wo, const float* __restrict__ wc){
    int idx = blockIdx.x*blockDim.x + threadIdx.x;
    if (idx >= Ff*NG) return;
    int k = idx >> 12, c = idx & (NG-1);
    int g = c & 3, hh = c >> 2;
    int cb = hh>>8, bbp = hh&255, rb = k>>7, aa = k&127;
    const float* w = (g==0)?wf:(g==1)?wi:(g==2)?wo:wc;
    int m = rb*4+cb;
    d_Wcat[idx] = c_SG[m]*w[((size_t)c_CM[m]*128+aa)*256+bbp];
}
__global__ void k_build_u(const float* __restrict__ uf, const float* __restrict__ ui,
                          const float* __restrict__ uo, const float* __restrict__ uc){
    int idx = blockIdx.x*blockDim.x + threadIdx.x;
    if (idx >= Hh*NG) return;
    int k = idx >> 12, c = idx & (NG-1);
    int g = c & 3, hh = c >> 2;
    int cb = hh>>8, bbp = hh&255, rb = k>>8, aa = k&255;
    const float* u = (g==0)?uf:(g==1)?ui:(g==2)?uo:uc;
    int m = rb*4+cb;
    float v = c_SG[m]*u[((size_t)c_CM[m]*256+aa)*256+bbp];
    __nv_bfloat16 hi = __float2bfloat16_rn(v);
    d_Ubhi[idx] = hi;
    d_Ublo[idx] = __float2bfloat16_rn(v - __bfloat162float(hi));
}
__global__ void k_build_misc(const float* __restrict__ bf, const float* __restrict__ bi,
                             const float* __restrict__ bo, const float* __restrict__ bc){
    int idx = blockIdx.x*blockDim.x + threadIdx.x;
    if (idx == 0) g_bar = 0u;
    if (idx < NG){
        int g = idx & 3, hh = idx >> 2;
        const float* b = (g==0)?bf:(g==1)?bi:(g==2)?bo:bc;
        d_Bcat[idx] = b[hh];
    }
}

// ---- input GEMM: G = x @ Wcat + Bcat ----
__global__ __launch_bounds__(256) void k_gemm_in(const float* __restrict__ X){
    __shared__ __align__(16) float As[8][128];
    __shared__ __align__(16) float Bs[8][128];
    const int bn = blockIdx.x, bm = blockIdx.y, tid = threadIdx.x;
    const int tx = tid&15, ty = tid>>4;
    const int row0 = bm*128, col0 = bn*128;
    float acc[8][8];
#pragma unroll
    for (int i=0;i<8;i++)
#pragma unroll
        for (int j=0;j<8;j++) acc[i][j]=0.f;
    const int am = tid>>1, ak = (tid&1)*4, bk = tid>>5, bn4 = (tid&31)*4;
    for (int k0=0;k0<Ff;k0+=8){
        float4 av = *(const float4*)&X[(size_t)(row0+am)*Ff + k0+ak];
        float4 bv = *(const float4*)&d_Wcat[(size_t)(k0+bk)*NG + col0+bn4];
        As[ak+0][am]=av.x; As[ak+1][am]=av.y; As[ak+2][am]=av.z; As[ak+3][am]=av.w;
        *(float4*)&Bs[bk][bn4] = bv;
        __syncthreads();
#pragma unroll
        for (int kk=0;kk<8;kk++){
            float a[8], b[8];
            *(float4*)(a)   = *(float4*)&As[kk][ty*8];
            *(float4*)(a+4) = *(float4*)&As[kk][ty*8+4];
            *(float4*)(b)   = *(float4*)&Bs[kk][tx*8];
            *(float4*)(b+4) = *(float4*)&Bs[kk][tx*8+4];
#pragma unroll
            for (int i=0;i<8;i++)
#pragma unroll
                for (int j=0;j<8;j++) acc[i][j] = fmaf(a[i], b[j], acc[i][j]);
        }
        __syncthreads();
    }
#pragma unroll
    for (int i=0;i<8;i++){
        size_t row = (size_t)(row0+ty*8+i);
#pragma unroll
        for (int j=0;j<8;j+=4){
            int col = col0+tx*8+j;
            float4 o;
            o.x=acc[i][j]+d_Bcat[col]; o.y=acc[i][j+1]+d_Bcat[col+1];
            o.z=acc[i][j+2]+d_Bcat[col+2]; o.w=acc[i][j+3]+d_Bcat[col+3];
            *(float4*)&d_G[row*NG+col] = o;
        }
    }
}

// ---- persistent HMMA recurrence ----
// smem: UHI [1024 rows x 80B] | ULO | HS[2 bufs][2 comps][64 rows x 144B] | exch f32[64][33]
#define OFF_ULO  81920
#define OFF_HS   163840
#define HS_BUF   18432
#define HS_COMP  9216
#define OFF_EX   200704
#define RSMEM    (200704 + 8448)

__device__ __forceinline__ void grid_bar(unsigned target){
    __syncthreads();
    if (threadIdx.x == 0){
        __threadfence();
        atomicAdd(&g_bar, 1u);
        while (*(volatile unsigned*)&g_bar < target) { }
        __threadfence();
    }
    __syncthreads();
}

__global__ __launch_bounds__(256,1) void k_recur_mma(){
    extern __shared__ char sm[];
    const int tid = threadIdx.x, lane = tid&31, w = tid>>5;
    const int blk = blockIdx.x;
    const int c0 = blk*32, u0 = blk*8;
    const int wm = w&3, wn = w>>2;
    char* UHI = sm;
    char* ULO = sm + OFF_ULO;
    char* HSB = sm + OFF_HS;
    float* exch = (float*)(sm + OFF_EX);

    // U slice (hi+lo) into padded smem rows (80B stride -> conflict-free ldmatrix.trans)
    for (int i = tid; i < 1024*4; i += 256){
        int k = i>>2, s = i&3;
        *(uint4*)(UHI + k*80 + s*16) =
            *(const uint4*)((const char*)(d_Ubhi + (size_t)k*NG + c0) + s*16);
        *(uint4*)(ULO + k*80 + s*16) =
            *(const uint4*)((const char*)(d_Ublo + (size_t)k*NG + c0) + s*16);
    }

    float cst[2] = {0.f, 0.f};
    const int pb = tid>>2;           // pointwise batch row
    const int pu = (tid&3)*2;        // pointwise unit pair base

    for (int t = 0; t < Tt; t++){
        if (t > 0){
            const char* hhi = (const char*)d_h2hi[(t-1)&1];
            const char* hlo = (const char*)d_h2lo[(t-1)&1];
            // stage chunk 0 (ldcg: bypass L1 — data written by other SMs last step)
#pragma unroll
            for (int j = 0; j < 4; j++){
                int i = tid + j*256; int comp = i>>9, r = (i>>3)&63, s = i&7;
                uint4 v = __ldcg((const uint4*)((comp?hlo:hhi) + r*2048 + s*16));
                *(uint4*)(HSB + comp*HS_COMP + r*144 + s*16) = v;
            }
            __syncthreads();

            float acc[6][4];
#pragma unroll
            for (int p=0;p<6;p++)
#pragma unroll
                for (int q=0;q<4;q++) acc[p][q]=0.f;

            for (int kc = 0; kc < 16; kc++){
                uint4 pre[4];
                if (kc < 15){
#pragma unroll
                    for (int j = 0; j < 4; j++){
                        int i = tid + j*256; int comp = i>>9, r = (i>>3)&63, s = i&7;
                        pre[j] = __ldcg((const uint4*)((comp?hlo:hhi) + r*2048 + (kc+1)*128 + s*16));
                    }
                }
                char* hs = HSB + (kc&1)*HS_BUF;
#pragma unroll
                for (int ks = 0; ks < 4; ks++){
                    uint32_t ah[4], al[4], bh[4], bl[4];
                    uint32_t aoff = (wm*16 + (lane&15))*144 + ks*32 + (lane>>4)*16;
                    LDSM4(ah, smem_u32(hs + aoff));
                    LDSM4(al, smem_u32(hs + HS_COMP + aoff));
                    uint32_t brow = kc*64 + ks*16 + (lane&15);
                    uint32_t boff = brow*80 + wn*32 + (lane>>4)*16;
                    LDSM4T(bh, smem_u32(UHI + boff));
                    LDSM4T(bl, smem_u32(ULO + boff));
                    MMA16816(acc[0], ah, bh[0], bh[1]);
                    MMA16816(acc[1], ah, bl[0], bl[1]);
                    MMA16816(acc[2], al, bh[0], bh[1]);
                    MMA16816(acc[3], ah, bh[2], bh[3]);
                    MMA16816(acc[4], ah, bl[2], bl[3]);
                    MMA16816(acc[5], al, bh[2], bh[3]);
                }
                if (kc < 15){
                    char* nb = HSB + ((kc+1)&1)*HS_BUF;
#pragma unroll
                    for (int j = 0; j < 4; j++){
                        int i = tid + j*256; int comp = i>>9, r = (i>>3)&63, s = i&7;
                        *(uint4*)(nb + comp*HS_COMP + r*144 + s*16) = pre[j];
                    }
                    __syncthreads();
                }
            }
            // write Z tile to exchange: rows = batch, cols = 32 local (4u+g)
            {
                int r0 = wm*16 + (lane>>2);
                int cb = wn*16 + (lane&3)*2;
                float s0[4], s1[4];
#pragma unroll
                for (int q=0;q<4;q++){
                    s0[q] = acc[0][q] + acc[1][q] + acc[2][q];
                    s1[q] = acc[3][q] + acc[4][q] + acc[5][q];
                }
                exch[r0*33 + cb]       = s0[0];
                exch[r0*33 + cb + 1]   = s0[1];
                exch[(r0+8)*33 + cb]   = s0[2];
                exch[(r0+8)*33 + cb+1] = s0[3];
                exch[r0*33 + cb + 8]       = s1[0];
                exch[r0*33 + cb + 9]       = s1[1];
                exch[(r0+8)*33 + cb + 8]   = s1[2];
                exch[(r0+8)*33 + cb + 9]   = s1[3];
            }
            __syncthreads();
        }

        // pointwise: thread -> (batch pb, units pu, pu+1); cell state in regs
#pragma unroll
        for (int j = 0; j < 2; j++){
            int u = pu + j;
            float4 g = *(const float4*)&d_G[((size_t)t*Bb + pb)*NG + c0 + 4*u];
            float zf = g.x, zi = g.y, zo = g.z, za = g.w;
            if (t > 0){
                zf += exch[pb*33 + 4*u];
                zi += exch[pb*33 + 4*u + 1];
                zo += exch[pb*33 + 4*u + 2];
                za += exch[pb*33 + 4*u + 3];
            }
            float f  = 1.f/(1.f+expf(-zf));
            float i2 = 1.f/(1.f+expf(-zi));
            float o  = 1.f/(1.f+expf(-zo));
            float cc = i2*tanhf(za) + f*cst[j];
            cst[j] = cc;
            float hv = o*tanhf(cc);
            d_Hbuf[((size_t)t*Bb + pb)*Hh + u0 + u] = hv;
            __nv_bfloat16 hb = __float2bfloat16_rn(hv);
            d_h2hi[t&1][pb*Hh + u0 + u] = hb;
            d_h2lo[t&1][pb*Hh + u0 + u] = __float2bfloat16_rn(hv - __bfloat162float(hb));
        }
        grid_bar((unsigned)(t+1) * NBLK);
    }
}

// ---- output GEMM: Out = Hbuf @ fco_w + fco_b ----
__global__ __launch_bounds__(256) void k_gemm_out(const float* __restrict__ Wout,
                                                  const float* __restrict__ bout,
                                                  float* __restrict__ Out){
    __shared__ __align__(16) float As[8][128];
    __shared__ __align__(16) float Bs[8][128];
    const int bn = blockIdx.x, bm = blockIdx.y, tid = threadIdx.x;
    const int tx = tid&15, ty = tid>>4;
    const int row0 = bm*128, col0 = bn*128;
    float acc[8][8];
#pragma unroll
    for (int i=0;i<8;i++)
#pragma unroll
        for (int j=0;j<8;j++) acc[i][j]=0.f;
    const int am = tid>>1, ak = (tid&1)*4, bk = tid>>5, bn4 = (tid&31)*4;
    for (int k0=0;k0<Hh;k0+=8){
        float4 av = *(const float4*)&d_Hbuf[(size_t)(row0+am)*Hh + k0+ak];
        As[ak+0][am]=av.x; As[ak+1][am]=av.y; As[ak+2][am]=av.z; As[ak+3][am]=av.w;
#pragma unroll
        for (int e=0;e<4;e++){
            int n = col0+bn4+e;
            Bs[bk][bn4+e] = (n < OUTF) ? Wout[(size_t)(k0+bk)*OUTF + n] : 0.f;
        }
        __syncthreads();
#pragma unroll
        for (int kk=0;kk<8;kk++){
            float a[8], b[8];
            *(float4*)(a)   = *(float4*)&As[kk][ty*8];
            *(float4*)(a+4) = *(float4*)&As[kk][ty*8+4];
            *(float4*)(b)   = *(float4*)&Bs[kk][tx*8];
            *(float4*)(b+4) = *(float4*)&Bs[kk][tx*8+4];
#pragma unroll
            for (int i=0;i<8;i++)
#pragma unroll
                for (int j=0;j<8;j++) acc[i][j] = fmaf(a[i], b[j], acc[i][j]);
        }
        __syncthreads();
    }
#pragma unroll
    for (int i=0;i<8;i++){
        size_t row = (size_t)(row0+ty*8+i);
#pragma unroll
        for (int j=0;j<8;j++){
            int col = col0+tx*8+j;
            if (col < OUTF) Out[row*OUTF+col] = acc[i][j] + bout[col];
        }
    }
}

// ---- launch ----
extern "C" void kernel_launch(void* const* d_in, const int* in_sizes, int n_in,
                              void* d_out, int out_size){
    (void)in_sizes; (void)n_in; (void)out_size;
    const float* x     = (const float*)d_in[0];
    const float* wfx_w = (const float*)d_in[1];
    const float* wfx_b = (const float*)d_in[2];
    const float* wix_w = (const float*)d_in[3];
    const float* wix_b = (const float*)d_in[4];
    const float* wox_w = (const float*)d_in[5];
    const float* wox_b = (const float*)d_in[6];
    const float* wcx_w = (const float*)d_in[7];
    const float* wcx_b = (const float*)d_in[8];
    const float* ufh_w = (const float*)d_in[9];
    const float* uih_w = (const float*)d_in[10];
    const float* uoh_w = (const float*)d_in[11];
    const float* uch_w = (const float*)d_in[12];
    const float* fco_w = (const float*)d_in[13];
    const float* fco_b = (const float*)d_in[14];
    float* out = (float*)d_out;

    cudaFuncSetAttribute(k_recur_mma, cudaFuncAttributeMaxDynamicSharedMemorySize, RSMEM);

    k_build_w<<<(Ff*NG + 255)/256, 256>>>(wfx_w, wix_w, wox_w, wcx_w);
    k_build_u<<<(Hh*NG + 255)/256, 256>>>(ufh_w, uih_w, uoh_w, uch_w);
    k_build_misc<<<(NG + 255)/256, 256>>>(wfx_b, wix_b, wox_b, wcx_b);

    k_gemm_in<<<dim3(NG/128, TBm/128), 256>>>(x);

    k_recur_mma<<<NBLK, 256, RSMEM>>>();

    k_gemm_out<<<dim3((OUTF+127)/128, TBm/128), 256>>>(fco_w, fco_b, out);
}

// round 7
// speedup vs baseline: 2.0579x; 1.2065x over previous
#include <cuda_runtime.h>
#include <cuda_bf16.h>
#include <cstdint>
#include <math.h>

#define Tt 128
#define Bb 64
#define Ff 512
#define Hh 1024
#define NG 4096
#define TBm 8192
#define OUTF 513
#define NBLK 128

static __device__ float d_Bcat[NG];
static __device__ float d_G[(size_t)TBm*NG];
static __device__ float d_Hbuf[(size_t)TBm*Hh];
static __device__ __nv_bfloat16 d_Wbhi[(size_t)Ff*NG];
static __device__ __nv_bfloat16 d_Wblo[(size_t)Ff*NG];
static __device__ __nv_bfloat16 d_Xhi[(size_t)TBm*Ff];
static __device__ __nv_bfloat16 d_Xlo[(size_t)TBm*Ff];
static __device__ __nv_bfloat16 d_Ubhi[(size_t)Hh*NG];
static __device__ __nv_bfloat16 d_Ublo[(size_t)Hh*NG];
static __device__ __nv_bfloat16 d_h2hi[2][Bb*Hh];
static __device__ __nv_bfloat16 d_h2lo[2][Bb*Hh];
static __device__ unsigned g_bar;

__constant__ int   c_CM[16] = {0,1,2,3, 1,0,3,2, 2,3,0,1, 3,2,1,0};
__constant__ float c_SG[16] = {1,1,1,1, -1,1,1,-1, -1,-1,1,1, -1,1,-1,1};

// ---- PTX helpers (sm_80-baseline, valid on sm_103) ----
__device__ __forceinline__ uint32_t smem_u32(const void* p){
    uint32_t a; asm("{ .reg .u64 t; cvta.to.shared.u64 t, %1; cvt.u32.u64 %0, t; }":"=r"(a):"l"(p)); return a;
}
#define LDSM4(r,a) asm volatile("ldmatrix.sync.aligned.m8n8.x4.shared.b16 {%0,%1,%2,%3}, [%4];" \
    :"=r"((r)[0]),"=r"((r)[1]),"=r"((r)[2]),"=r"((r)[3]):"r"(a))
#define LDSM4T(r,a) asm volatile("ldmatrix.sync.aligned.m8n8.x4.trans.shared.b16 {%0,%1,%2,%3}, [%4];" \
    :"=r"((r)[0]),"=r"((r)[1]),"=r"((r)[2]),"=r"((r)[3]):"r"(a))
#define MMA16816(c,a,b0,b1) asm volatile( \
    "mma.sync.aligned.m16n8k16.row.col.f32.bf16.bf16.f32 {%0,%1,%2,%3},{%4,%5,%6,%7},{%8,%9},{%0,%1,%2,%3};" \
    :"+f"((c)[0]),"+f"((c)[1]),"+f"((c)[2]),"+f"((c)[3]) \
    :"r"((a)[0]),"r"((a)[1]),"r"((a)[2]),"r"((a)[3]),"r"(b0),"r"(b1))
#define CPA16(dst,src) asm volatile("cp.async.cg.shared.global [%0], [%1], 16;"::"r"(dst),"l"(src))
#define CPA_COMMIT()   asm volatile("cp.async.commit_group;":::"memory")
#define CPA_WAIT1()    asm volatile("cp.async.wait_group 1;":::"memory")
#define CPA_WAIT0()    asm volatile("cp.async.wait_group 0;":::"memory")

// ---- builds (gate-interleaved cols: col = 4h + g) ----
__global__ void k_build_wbf(const float* __restrict__ wf, const float* __restrict__ wi,
                            const float* __restrict__ wo, const float* __restrict__ wc){
    int idx = blockIdx.x*blockDim.x + threadIdx.x;
    if (idx >= Ff*NG) return;
    int k = idx >> 12, c = idx & (NG-1);
    int g = c & 3, hh = c >> 2;
    int cb = hh>>8, bbp = hh&255, rb = k>>7, aa = k&127;
    const float* w = (g==0)?wf:(g==1)?wi:(g==2)?wo:wc;
    int m = rb*4+cb;
    float v = c_SG[m]*w[((size_t)c_CM[m]*128+aa)*256+bbp];
    __nv_bfloat16 hi = __float2bfloat16_rn(v);
    d_Wbhi[idx] = hi;
    d_Wblo[idx] = __float2bfloat16_rn(v - __bfloat162float(hi));
}
__global__ void k_split_x(const float* __restrict__ x){
    int idx = blockIdx.x*blockDim.x + threadIdx.x;
    if (idx >= TBm*Ff) return;
    float v = x[idx];
    __nv_bfloat16 hi = __float2bfloat16_rn(v);
    d_Xhi[idx] = hi;
    d_Xlo[idx] = __float2bfloat16_rn(v - __bfloat162float(hi));
}
__global__ void k_build_u(const float* __restrict__ uf, const float* __restrict__ ui,
                          const float* __restrict__ uo, const float* __restrict__ uc){
    int idx = blockIdx.x*blockDim.x + threadIdx.x;
    if (idx >= Hh*NG) return;
    int k = idx >> 12, c = idx & (NG-1);
    int g = c & 3, hh = c >> 2;
    int cb = hh>>8, bbp = hh&255, rb = k>>8, aa = k&255;
    const float* u = (g==0)?uf:(g==1)?ui:(g==2)?uo:uc;
    int m = rb*4+cb;
    float v = c_SG[m]*u[((size_t)c_CM[m]*256+aa)*256+bbp];
    __nv_bfloat16 hi = __float2bfloat16_rn(v);
    d_Ubhi[idx] = hi;
    d_Ublo[idx] = __float2bfloat16_rn(v - __bfloat162float(hi));
}
__global__ void k_build_misc(const float* __restrict__ bf, const float* __restrict__ bi,
                             const float* __restrict__ bo, const float* __restrict__ bc){
    int idx = blockIdx.x*blockDim.x + threadIdx.x;
    if (idx == 0) g_bar = 0u;
    if (idx < NG){
        int g = idx & 3, hh = idx >> 2;
        const float* b = (g==0)?bf:(g==1)?bi:(g==2)?bo:bc;
        d_Bcat[idx] = b[hh];
    }
}

// ---- HMMA input GEMM: G = Xhi*Whi + Xhi*Wlo + Xlo*Whi + Bcat ----
// Block tile 128x128, K-chunk 64, 8 warps (wm 0..3: m32, wn 0..1: n64)
#define IA_STR 144
#define IB_STR 272
#define IA_SZ  (128*IA_STR)            // one comp
#define IB_SZ  (64*IB_STR)
#define IBUF   (2*IA_SZ + 2*IB_SZ)     // 71680
#define ISMEM  (2*IBUF)                // 143360

__device__ __forceinline__ void gi_load(char* buf, int row0, int col0, int kc, int tid){
    const __nv_bfloat16* Xc[2] = {d_Xhi, d_Xlo};
    const __nv_bfloat16* Wc[2] = {d_Wbhi, d_Wblo};
#pragma unroll
    for (int j = 0; j < 8; j++){
        int i = tid + j*256;
        int comp = i >> 10, rem = i & 1023, r = rem >> 3, s = rem & 7;
        const char* src = (const char*)(Xc[comp] + (size_t)(row0 + r)*Ff + kc*64 + s*8);
        CPA16(smem_u32(buf + comp*IA_SZ + r*IA_STR + s*16), src);
    }
    char* bbuf = buf + 2*IA_SZ;
#pragma unroll
    for (int j = 0; j < 8; j++){
        int i = tid + j*256;
        int comp = i >> 10, rem = i & 1023, r = rem >> 4, s = rem & 15;
        const char* src = (const char*)(Wc[comp] + (size_t)(kc*64 + r)*NG + col0 + s*8);
        CPA16(smem_u32(bbuf + comp*IB_SZ + r*IB_STR + s*16), src);
    }
    CPA_COMMIT();
}

__global__ __launch_bounds__(256,1) void k_gemm_in_mma(){
    extern __shared__ char sm[];
    const int tid = threadIdx.x, lane = tid&31, w = tid>>5;
    const int wm = w&3, wn = w>>2;
    const int col0 = blockIdx.x*128, row0 = blockIdx.y*128;

    float acc[2][8][4];
#pragma unroll
    for (int mi=0;mi<2;mi++)
#pragma unroll
        for (int nj=0;nj<8;nj++)
#pragma unroll
            for (int q=0;q<4;q++) acc[mi][nj][q]=0.f;

    gi_load(sm, row0, col0, 0, tid);

    for (int kc = 0; kc < 8; kc++){
        if (kc < 7) gi_load(sm + ((kc+1)&1)*IBUF, row0, col0, kc+1, tid);
        if (kc < 7) CPA_WAIT1(); else CPA_WAIT0();
        __syncthreads();
        char* abuf = sm + (kc&1)*IBUF;
        char* bbuf = abuf + 2*IA_SZ;
#pragma unroll
        for (int ks = 0; ks < 4; ks++){
            uint32_t ah[2][4], al[2][4], bh[4][4], bl[4][4];
#pragma unroll
            for (int mi = 0; mi < 2; mi++){
                uint32_t aoff = (wm*32 + mi*16 + (lane&15))*IA_STR + ks*32 + (lane>>4)*16;
                LDSM4(ah[mi], smem_u32(abuf + aoff));
                LDSM4(al[mi], smem_u32(abuf + IA_SZ + aoff));
            }
#pragma unroll
            for (int ni = 0; ni < 4; ni++){
                uint32_t boff = (ks*16 + (lane&15))*IB_STR + wn*128 + ni*32 + (lane>>4)*16;
                LDSM4T(bh[ni], smem_u32(bbuf + boff));
                LDSM4T(bl[ni], smem_u32(bbuf + IB_SZ + boff));
            }
#pragma unroll
            for (int mi = 0; mi < 2; mi++)
#pragma unroll
                for (int ni = 0; ni < 4; ni++){
                    MMA16816(acc[mi][2*ni],   ah[mi], bh[ni][0], bh[ni][1]);
                    MMA16816(acc[mi][2*ni],   ah[mi], bl[ni][0], bl[ni][1]);
                    MMA16816(acc[mi][2*ni],   al[mi], bh[ni][0], bh[ni][1]);
                    MMA16816(acc[mi][2*ni+1], ah[mi], bh[ni][2], bh[ni][3]);
                    MMA16816(acc[mi][2*ni+1], ah[mi], bl[ni][2], bl[ni][3]);
                    MMA16816(acc[mi][2*ni+1], al[mi], bh[ni][2], bh[ni][3]);
                }
        }
        __syncthreads();
    }
    // epilogue: + Bcat, write G
#pragma unroll
    for (int mi = 0; mi < 2; mi++){
        int r = wm*32 + mi*16 + (lane>>2);
#pragma unroll
        for (int nj = 0; nj < 8; nj++){
            int c = col0 + wn*64 + nj*8 + (lane&3)*2;
            float2 bc = *(const float2*)&d_Bcat[c];
            size_t g0 = (size_t)(row0 + r)*NG + c;
            *(float2*)&d_G[g0] = make_float2(acc[mi][nj][0] + bc.x, acc[mi][nj][1] + bc.y);
            *(float2*)&d_G[g0 + 8*NG] = make_float2(acc[mi][nj][2] + bc.x, acc[mi][nj][3] + bc.y);
        }
    }
}

// ---- persistent HMMA recurrence (unchanged from R6) ----
#define OFF_ULO  81920
#define OFF_HS   163840
#define HS_BUF   18432
#define HS_COMP  9216
#define OFF_EX   200704
#define RSMEM    (200704 + 8448)

__device__ __forceinline__ void grid_bar(unsigned target){
    __syncthreads();
    if (threadIdx.x == 0){
        __threadfence();
        atomicAdd(&g_bar, 1u);
        while (*(volatile unsigned*)&g_bar < target) { }
        __threadfence();
    }
    __syncthreads();
}

__global__ __launch_bounds__(256,1) void k_recur_mma(){
    extern __shared__ char sm[];
    const int tid = threadIdx.x, lane = tid&31, w = tid>>5;
    const int blk = blockIdx.x;
    const int c0 = blk*32, u0 = blk*8;
    const int wm = w&3, wn = w>>2;
    char* UHI = sm;
    char* ULO = sm + OFF_ULO;
    char* HSB = sm + OFF_HS;
    float* exch = (float*)(sm + OFF_EX);

    for (int i = tid; i < 1024*4; i += 256){
        int k = i>>2, s = i&3;
        *(uint4*)(UHI + k*80 + s*16) =
            *(const uint4*)((const char*)(d_Ubhi + (size_t)k*NG + c0) + s*16);
        *(uint4*)(ULO + k*80 + s*16) =
            *(const uint4*)((const char*)(d_Ublo + (size_t)k*NG + c0) + s*16);
    }

    float cst[2] = {0.f, 0.f};
    const int pb = tid>>2;
    const int pu = (tid&3)*2;

    for (int t = 0; t < Tt; t++){
        if (t > 0){
            const char* hhi = (const char*)d_h2hi[(t-1)&1];
            const char* hlo = (const char*)d_h2lo[(t-1)&1];
#pragma unroll
            for (int j = 0; j < 4; j++){
                int i = tid + j*256; int comp = i>>9, r = (i>>3)&63, s = i&7;
                uint4 v = __ldcg((const uint4*)((comp?hlo:hhi) + r*2048 + s*16));
                *(uint4*)(HSB + comp*HS_COMP + r*144 + s*16) = v;
            }
            __syncthreads();

            float acc[6][4];
#pragma unroll
            for (int p=0;p<6;p++)
#pragma unroll
                for (int q=0;q<4;q++) acc[p][q]=0.f;

            for (int kc = 0; kc < 16; kc++){
                uint4 pre[4];
                if (kc < 15){
#pragma unroll
                    for (int j = 0; j < 4; j++){
                        int i = tid + j*256; int comp = i>>9, r = (i>>3)&63, s = i&7;
                        pre[j] = __ldcg((const uint4*)((comp?hlo:hhi) + r*2048 + (kc+1)*128 + s*16));
                    }
                }
                char* hs = HSB + (kc&1)*HS_BUF;
#pragma unroll
                for (int ks = 0; ks < 4; ks++){
                    uint32_t ah[4], al[4], bh[4], bl[4];
                    uint32_t aoff = (wm*16 + (lane&15))*144 + ks*32 + (lane>>4)*16;
                    LDSM4(ah, smem_u32(hs + aoff));
                    LDSM4(al, smem_u32(hs + HS_COMP + aoff));
                    uint32_t brow = kc*64 + ks*16 + (lane&15);
                    uint32_t boff = brow*80 + wn*32 + (lane>>4)*16;
                    LDSM4T(bh, smem_u32(UHI + boff));
                    LDSM4T(bl, smem_u32(ULO + boff));
                    MMA16816(acc[0], ah, bh[0], bh[1]);
                    MMA16816(acc[1], ah, bl[0], bl[1]);
                    MMA16816(acc[2], al, bh[0], bh[1]);
                    MMA16816(acc[3], ah, bh[2], bh[3]);
                    MMA16816(acc[4], ah, bl[2], bl[3]);
                    MMA16816(acc[5], al, bh[2], bh[3]);
                }
                if (kc < 15){
                    char* nb = HSB + ((kc+1)&1)*HS_BUF;
#pragma unroll
                    for (int j = 0; j < 4; j++){
                        int i = tid + j*256; int comp = i>>9, r = (i>>3)&63, s = i&7;
                        *(uint4*)(nb + comp*HS_COMP + r*144 + s*16) = pre[j];
                    }
                    __syncthreads();
                }
            }
            {
                int r0 = wm*16 + (lane>>2);
                int cb = wn*16 + (lane&3)*2;
                float s0[4], s1[4];
#pragma unroll
                for (int q=0;q<4;q++){
                    s0[q] = acc[0][q] + acc[1][q] + acc[2][q];
                    s1[q] = acc[3][q] + acc[4][q] + acc[5][q];
                }
                exch[r0*33 + cb]       = s0[0];
                exch[r0*33 + cb + 1]   = s0[1];
                exch[(r0+8)*33 + cb]   = s0[2];
                exch[(r0+8)*33 + cb+1] = s0[3];
                exch[r0*33 + cb + 8]       = s1[0];
                exch[r0*33 + cb + 9]       = s1[1];
                exch[(r0+8)*33 + cb + 8]   = s1[2];
                exch[(r0+8)*33 + cb + 9]   = s1[3];
            }
            __syncthreads();
        }

#pragma unroll
        for (int j = 0; j < 2; j++){
            int u = pu + j;
            float4 g = *(const float4*)&d_G[((size_t)t*Bb + pb)*NG + c0 + 4*u];
            float zf = g.x, zi = g.y, zo = g.z, za = g.w;
            if (t > 0){
                zf += exch[pb*33 + 4*u];
                zi += exch[pb*33 + 4*u + 1];
                zo += exch[pb*33 + 4*u + 2];
                za += exch[pb*33 + 4*u + 3];
            }
            float f  = 1.f/(1.f+expf(-zf));
            float i2 = 1.f/(1.f+expf(-zi));
            float o  = 1.f/(1.f+expf(-zo));
            float cc = i2*tanhf(za) + f*cst[j];
            cst[j] = cc;
            float hv = o*tanhf(cc);
            d_Hbuf[((size_t)t*Bb + pb)*Hh + u0 + u] = hv;
            __nv_bfloat16 hb = __float2bfloat16_rn(hv);
            d_h2hi[t&1][pb*Hh + u0 + u] = hb;
            d_h2lo[t&1][pb*Hh + u0 + u] = __float2bfloat16_rn(hv - __bfloat162float(hb));
        }
        grid_bar((unsigned)(t+1) * NBLK);
    }
}

// ---- output GEMM: Out = Hbuf @ fco_w + fco_b ----
__global__ __launch_bounds__(256) void k_gemm_out(const float* __restrict__ Wout,
                                                  const float* __restrict__ bout,
                                                  float* __restrict__ Out){
    __shared__ __align__(16) float As[8][128];
    __shared__ __align__(16) float Bs[8][128];
    const int bn = blockIdx.x, bm = blockIdx.y, tid = threadIdx.x;
    const int tx = tid&15, ty = tid>>4;
    const int row0 = bm*128, col0 = bn*128;
    float acc[8][8];
#pragma unroll
    for (int i=0;i<8;i++)
#pragma unroll
        for (int j=0;j<8;j++) acc[i][j]=0.f;
    const int am = tid>>1, ak = (tid&1)*4, bk = tid>>5, bn4 = (tid&31)*4;
    for (int k0=0;k0<Hh;k0+=8){
        float4 av = *(const float4*)&d_Hbuf[(size_t)(row0+am)*Hh + k0+ak];
        As[ak+0][am]=av.x; As[ak+1][am]=av.y; As[ak+2][am]=av.z; As[ak+3][am]=av.w;
#pragma unroll
        for (int e=0;e<4;e++){
            int n = col0+bn4+e;
            Bs[bk][bn4+e] = (n < OUTF) ? Wout[(size_t)(k0+bk)*OUTF + n] : 0.f;
        }
        __syncthreads();
#pragma unroll
        for (int kk=0;kk<8;kk++){
            float a[8], b[8];
            *(float4*)(a)   = *(float4*)&As[kk][ty*8];
            *(float4*)(a+4) = *(float4*)&As[kk][ty*8+4];
            *(float4*)(b)   = *(float4*)&Bs[kk][tx*8];
            *(float4*)(b+4) = *(float4*)&Bs[kk][tx*8+4];
#pragma unroll
            for (int i=0;i<8;i++)
#pragma unroll
                for (int j=0;j<8;j++) acc[i][j] = fmaf(a[i], b[j], acc[i][j]);
        }
        __syncthreads();
    }
#pragma unroll
    for (int i=0;i<8;i++){
        size_t row = (size_t)(row0+ty*8+i);
#pragma unroll
        for (int j=0;j<8;j++){
            int col = col0+tx*8+j;
            if (col < OUTF) Out[row*OUTF+col] = acc[i][j] + bout[col];
        }
    }
}

// ---- launch ----
extern "C" void kernel_launch(void* const* d_in, const int* in_sizes, int n_in,
                              void* d_out, int out_size){
    (void)in_sizes; (void)n_in; (void)out_size;
    const float* x     = (const float*)d_in[0];
    const float* wfx_w = (const float*)d_in[1];
    const float* wfx_b = (const float*)d_in[2];
    const float* wix_w = (const float*)d_in[3];
    const float* wix_b = (const float*)d_in[4];
    const float* wox_w = (const float*)d_in[5];
    const float* wox_b = (const float*)d_in[6];
    const float* wcx_w = (const float*)d_in[7];
    const float* wcx_b = (const float*)d_in[8];
    const float* ufh_w = (const float*)d_in[9];
    const float* uih_w = (const float*)d_in[10];
    const float* uoh_w = (const float*)d_in[11];
    const float* uch_w = (const float*)d_in[12];
    const float* fco_w = (const float*)d_in[13];
    const float* fco_b = (const float*)d_in[14];
    float* out = (float*)d_out;

    cudaFuncSetAttribute(k_recur_mma, cudaFuncAttributeMaxDynamicSharedMemorySize, RSMEM);
    cudaFuncSetAttribute(k_gemm_in_mma, cudaFuncAttributeMaxDynamicSharedMemorySize, ISMEM);

    k_build_wbf<<<(Ff*NG + 255)/256, 256>>>(wfx_w, wix_w, wox_w, wcx_w);
    k_split_x<<<(TBm*Ff + 255)/256, 256>>>(x);
    k_build_u<<<(Hh*NG + 255)/256, 256>>>(ufh_w, uih_w, uoh_w, uch_w);
    k_build_misc<<<(NG + 255)/256, 256>>>(wfx_b, wix_b, wox_b, wcx_b);

    k_gemm_in_mma<<<dim3(NG/128, TBm/128), 256, ISMEM>>>();

    k_recur_mma<<<NBLK, 256, RSMEM>>>();

    k_gemm_out<<<dim3((OUTF+127)/128, TBm/128), 256>>>(fco_w, fco_b, out);
}